// round 1
// baseline (speedup 1.0000x reference)
#include <cuda_runtime.h>
#include <math.h>

#define PI_F 3.14159265358979323846f

// One block per batch image (128 blocks x 256 threads).
// Threads 0..195: simulate one 4-qubit circuit per 2x2 patch, write 4 <Z> feats to smem.
// Then all 256 threads: FC1 (784->64, relu) with 4-way k-split + shfl reduce, FC2 (64->10).
__global__ __launch_bounds__(256, 1) void qnet_kernel(
    const float* __restrict__ x,      // [128,1,28,28]
    const float* __restrict__ weight, // [60]
    const float* __restrict__ fc1_w,  // [64,784]
    const float* __restrict__ fc1_b,  // [64]
    const float* __restrict__ fc2_w,  // [10,64]
    const float* __restrict__ fc2_b,  // [10]
    float* __restrict__ out)          // [128,10]
{
    __shared__ float scw[60], ssw[60];
    __shared__ float sfeat[784];
    __shared__ float sh[64];

    const int t = threadIdx.x;
    const int b = blockIdx.x;

    // Precompute cos/sin of half-angles for the 60 trainable params (per block).
    if (t < 60) {
        float sw, cw;
        sincosf(0.5f * weight[t], &sw, &cw);
        ssw[t] = sw; scw[t] = cw;
    }
    __syncthreads();

    if (t < 196) {
        const int pi_ = t / 14, pj = t % 14;
        const float* xb = x + b * 784 + (2 * pi_) * 28 + 2 * pj;
        const float px0 = xb[0], px1 = xb[1], px2 = xb[28], px3 = xb[29];

        // Rx(2*pi*x) on |0>: qubit state = (cos(pi x), -i sin(pi x))
        float c[4], s[4];
        sincosf(PI_F * px0, &s[0], &c[0]);
        sincosf(PI_F * px1, &s[1], &c[1]);
        sincosf(PI_F * px2, &s[2], &c[2]);
        sincosf(PI_F * px3, &s[3], &c[3]);

        // Product state: a[i] = (-i)^popc(i) * prod_q (bit? s : c)
        // index i: qubit0 = bit3 (weight 8), ..., qubit3 = bit0.
        float ar[16], ai[16];
        #pragma unroll
        for (int i = 0; i < 16; i++) {
            float m = ((i & 8) ? s[0] : c[0]) * ((i & 4) ? s[1] : c[1])
                    * ((i & 2) ? s[2] : c[2]) * ((i & 1) ? s[3] : c[3]);
            int pc = __popc(i) & 3;
            ar[i] = (pc == 0) ? m : ((pc == 2) ? -m : 0.f);
            ai[i] = (pc == 1) ? -m : ((pc == 3) ? m : 0.f);
        }

        #pragma unroll
        for (int layer = 0; layer < 5; layer++) {
            const int base = layer * 12;

            // Ry(p[q]) on each qubit: real rotation [[c,-s],[s,c]]
            #pragma unroll
            for (int q = 0; q < 4; q++) {
                const float cg = scw[base + q], sg = ssw[base + q];
                const int st = 8 >> q;
                #pragma unroll
                for (int i = 0; i < 16; i++) {
                    if (i & st) continue;
                    const int j = i | st;
                    float ar0 = ar[i], ai0 = ai[i], ar1 = ar[j], ai1 = ai[j];
                    ar[i] = cg * ar0 - sg * ar1; ai[i] = cg * ai0 - sg * ai1;
                    ar[j] = sg * ar0 + cg * ar1; ai[j] = sg * ai0 + cg * ai1;
                }
            }
            // Rz(p[4+q]): diag(e^{-i th/2}, e^{+i th/2})
            #pragma unroll
            for (int q = 0; q < 4; q++) {
                const float cg = scw[base + 4 + q], sg = ssw[base + 4 + q];
                const int st = 8 >> q;
                #pragma unroll
                for (int i = 0; i < 16; i++) {
                    const float sgn = (i & st) ? sg : -sg;
                    const float r = ar[i], im = ai[i];
                    ar[i] = cg * r - sgn * im;
                    ai[i] = cg * im + sgn * r;
                }
            }
            // Ry(p[8+q])
            #pragma unroll
            for (int q = 0; q < 4; q++) {
                const float cg = scw[base + 8 + q], sg = ssw[base + 8 + q];
                const int st = 8 >> q;
                #pragma unroll
                for (int i = 0; i < 16; i++) {
                    if (i & st) continue;
                    const int j = i | st;
                    float ar0 = ar[i], ai0 = ai[i], ar1 = ar[j], ai1 = ai[j];
                    ar[i] = cg * ar0 - sg * ar1; ai[i] = cg * ai0 - sg * ai1;
                    ar[j] = sg * ar0 + cg * ar1; ai[j] = sg * ai0 + cg * ai1;
                }
            }
            // CNOT ring 0->1->2->3->0 (layers 0..3 only)
            if (layer < 4) {
                #pragma unroll
                for (int q = 0; q < 4; q++) {
                    const int cb = 8 >> q, tb = 8 >> ((q + 1) & 3);
                    #pragma unroll
                    for (int i = 0; i < 16; i++) {
                        if ((i & cb) && !(i & tb)) {
                            const int j = i | tb;
                            float tr = ar[i]; ar[i] = ar[j]; ar[j] = tr;
                            float ti = ai[i]; ai[i] = ai[j]; ai[j] = ti;
                        }
                    }
                }
            }
        }

        // <Z_q> expectations
        float p[16];
        #pragma unroll
        for (int i = 0; i < 16; i++) p[i] = ar[i] * ar[i] + ai[i] * ai[i];
        #pragma unroll
        for (int q = 0; q < 4; q++) {
            const int st = 8 >> q;
            float e = 0.f;
            #pragma unroll
            for (int i = 0; i < 16; i++) e += (i & st) ? -p[i] : p[i];
            sfeat[t * 4 + q] = e;   // feature index (i*14+j)*4+q
        }
    }
    __syncthreads();

    // FC1: 64 outputs, each computed by 4 threads over 196-long k-slices (float4).
    {
        const int o = t >> 2, part = t & 3;
        const float4* wrow = (const float4*)(fc1_w + o * 784 + part * 196);
        const float4* frow = (const float4*)(sfeat + part * 196);
        float sum = 0.f;
        #pragma unroll 7
        for (int k = 0; k < 49; k++) {
            float4 w4 = wrow[k];
            float4 f4 = frow[k];
            sum += w4.x * f4.x + w4.y * f4.y + w4.z * f4.z + w4.w * f4.w;
        }
        // reduce 4 partials (consecutive lanes within a warp)
        sum += __shfl_xor_sync(0xffffffffu, sum, 1);
        sum += __shfl_xor_sync(0xffffffffu, sum, 2);
        if (part == 0) sh[o] = fmaxf(sum + fc1_b[o], 0.f);
    }
    __syncthreads();

    // FC2: 10 outputs
    if (t < 10) {
        float sum = fc2_b[t];
        const float* w2 = fc2_w + t * 64;
        #pragma unroll
        for (int k = 0; k < 64; k++) sum += w2[k] * sh[k];
        out[b * 10 + t] = sum;
    }
}

extern "C" void kernel_launch(void* const* d_in, const int* in_sizes, int n_in,
                              void* d_out, int out_size) {
    const float* x      = (const float*)d_in[0];
    const float* weight = (const float*)d_in[1];
    const float* fc1_w  = (const float*)d_in[2];
    const float* fc1_b  = (const float*)d_in[3];
    const float* fc2_w  = (const float*)d_in[4];
    const float* fc2_b  = (const float*)d_in[5];
    float* out = (float*)d_out;

    const int B = in_sizes[0] / 784;  // 128
    qnet_kernel<<<B, 256>>>(x, weight, fc1_w, fc1_b, fc2_w, fc2_b, out);
}

// round 3
// speedup vs baseline: 1.2311x; 1.2311x over previous
#include <cuda_runtime.h>
#include <math.h>

#define PI_F 3.14159265358979323846f

// One block per batch image (128 blocks x 256 threads).
// Preamble: 20 threads build the Euler-merged SU(2) matrix per (layer,qubit).
// Threads 0..195: simulate one 4-qubit circuit per 2x2 patch (layer 0 absorbed
// into the initial product state), write 4 <Z> feats to smem.
// Then FC1 (784->64, relu) with 4-way k-split + shfl reduce, FC2 (64->10).
__global__ __launch_bounds__(256, 1) void qnet_kernel(
    const float* __restrict__ x,      // [128,1,28,28]
    const float* __restrict__ weight, // [60]
    const float* __restrict__ fc1_w,  // [64,784]
    const float* __restrict__ fc1_b,  // [64]
    const float* __restrict__ fc2_w,  // [10,64]
    const float* __restrict__ fc2_b,  // [10]
    float* __restrict__ out)          // [128,10]
{
    __shared__ float4 ssu2[20];       // (ar, ai, br, bi) per (layer*4 + qubit)
    __shared__ float sfeat[784];
    __shared__ float sh[64];

    const int t = threadIdx.x;
    const int b = blockIdx.x;

    // U = Ry(c)*Rz(bb)*Ry(a) = [[alpha, -conj(beta)],[beta, conj(alpha)]]
    if (t < 20) {
        const int layer = t >> 2, q = t & 3;
        const int base = layer * 12;
        float sa, ca, sb, cb, sc, cc;
        sincosf(0.5f * weight[base + q],     &sa, &ca);
        sincosf(0.5f * weight[base + 4 + q], &sb, &cb);
        sincosf(0.5f * weight[base + 8 + q], &sc, &cc);
        const float ar =  cb * (cc * ca - sc * sa);
        const float ai = -sb * (cc * ca + sc * sa);
        const float br =  cb * (sc * ca + cc * sa);
        const float bi =  sb * (cc * sa - sc * ca);
        ssu2[t] = make_float4(ar, ai, br, bi);
    }
    __syncthreads();

    if (t < 196) {
        const int pi_ = t / 14, pj = t % 14;
        const float* xb = x + b * 784 + (2 * pi_) * 28 + 2 * pj;
        const float px0 = xb[0], px1 = xb[1], px2 = xb[28], px3 = xb[29];

        // Rx(2*pi*x)|0> = (cos(pi x), -i sin(pi x)); then apply layer-0 U_q.
        float cx[4], sx[4];
        sincosf(PI_F * px0, &sx[0], &cx[0]);
        sincosf(PI_F * px1, &sx[1], &cx[1]);
        sincosf(PI_F * px2, &sx[2], &cx[2]);
        sincosf(PI_F * px3, &sx[3], &cx[3]);

        float v0r[4], v0i[4], v1r[4], v1i[4];
        #pragma unroll
        for (int q = 0; q < 4; q++) {
            const float4 u = ssu2[q];
            // v0 = alpha*cx + i*conj(beta)*sx ; v1 = beta*cx - i*conj(alpha)*sx
            v0r[q] = u.x * cx[q] + u.w * sx[q];
            v0i[q] = u.y * cx[q] + u.z * sx[q];
            v1r[q] = u.z * cx[q] - u.y * sx[q];
            v1i[q] = u.w * cx[q] - u.x * sx[q];
        }

        // Product state via tree: w01 = v(q0) x v(q1), w23 = v(q2) x v(q3)
        float w01r[4], w01i[4], w23r[4], w23i[4];
        #pragma unroll
        for (int b0 = 0; b0 < 2; b0++) {
            const float x0r = b0 ? v1r[0] : v0r[0], x0i = b0 ? v1i[0] : v0i[0];
            const float y0r = b0 ? v1r[2] : v0r[2], y0i = b0 ? v1i[2] : v0i[2];
            #pragma unroll
            for (int b1 = 0; b1 < 2; b1++) {
                const float x1r = b1 ? v1r[1] : v0r[1], x1i = b1 ? v1i[1] : v0i[1];
                const float y1r = b1 ? v1r[3] : v0r[3], y1i = b1 ? v1i[3] : v0i[3];
                w01r[b0 * 2 + b1] = x0r * x1r - x0i * x1i;
                w01i[b0 * 2 + b1] = x0r * x1i + x0i * x1r;
                w23r[b0 * 2 + b1] = y0r * y1r - y0i * y1i;
                w23i[b0 * 2 + b1] = y0r * y1i + y0i * y1r;
            }
        }

        // a[i], i = (q0 q1 q2 q3) bits (q0 = bit3)
        float ar[16], ai[16];
        #pragma unroll
        for (int i = 0; i < 16; i++) {
            const int hi = i >> 2, lo = i & 3;
            ar[i] = w01r[hi] * w23r[lo] - w01i[hi] * w23i[lo];
            ai[i] = w01r[hi] * w23i[lo] + w01i[hi] * w23r[lo];
        }

        // Prefetch layer-1 gates; inside the loop prefetch next layer's gates
        // before doing this layer's arithmetic (hide LDS latency).
        float4 g0 = ssu2[4], g1 = ssu2[5], g2 = ssu2[6], g3 = ssu2[7];

        // Layers 1..4: CNOT ring then merged SU(2) per qubit
        #pragma unroll
        for (int layer = 1; layer < 5; layer++) {
            const float4 u0 = g0, u1 = g1, u2 = g2, u3 = g3;
            if (layer < 4) {
                g0 = ssu2[layer * 4 + 4]; g1 = ssu2[layer * 4 + 5];
                g2 = ssu2[layer * 4 + 6]; g3 = ssu2[layer * 4 + 7];
            }
            // CNOT ring 0->1->2->3->0
            #pragma unroll
            for (int q = 0; q < 4; q++) {
                const int cb = 8 >> q, tb = 8 >> ((q + 1) & 3);
                #pragma unroll
                for (int i = 0; i < 16; i++) {
                    if ((i & cb) && !(i & tb)) {
                        const int j = i | tb;
                        float tr = ar[i]; ar[i] = ar[j]; ar[j] = tr;
                        float ti = ai[i]; ai[i] = ai[j]; ai[j] = ti;
                    }
                }
            }
            // U per qubit: a0' = alpha a0 - conj(beta) a1 ; a1' = beta a0 + conj(alpha) a1
            #pragma unroll
            for (int q = 0; q < 4; q++) {
                const float4 u = (q == 0) ? u0 : (q == 1) ? u1 : (q == 2) ? u2 : u3;
                const int st = 8 >> q;
                #pragma unroll
                for (int i = 0; i < 16; i++) {
                    if (i & st) continue;
                    const int j = i | st;
                    const float a0r = ar[i], a0i = ai[i], a1r = ar[j], a1i = ai[j];
                    ar[i] = u.x * a0r - u.y * a0i - u.z * a1r - u.w * a1i;
                    ai[i] = u.x * a0i + u.y * a0r - u.z * a1i + u.w * a1r;
                    ar[j] = u.z * a0r - u.w * a0i + u.x * a1r + u.y * a1i;
                    ai[j] = u.z * a0i + u.w * a0r + u.x * a1i - u.y * a1r;
                }
            }
        }

        // <Z_q> expectations
        float p[16];
        #pragma unroll
        for (int i = 0; i < 16; i++) p[i] = ar[i] * ar[i] + ai[i] * ai[i];
        #pragma unroll
        for (int q = 0; q < 4; q++) {
            const int st = 8 >> q;
            float e = 0.f;
            #pragma unroll
            for (int i = 0; i < 16; i++) e += (i & st) ? -p[i] : p[i];
            sfeat[t * 4 + q] = e;   // feature index (i*14+j)*4+q
        }
    }
    __syncthreads();

    // FC1: 64 outputs, each computed by 4 threads over 196-long k-slices (float4).
    {
        const int o = t >> 2, part = t & 3;
        const float4* wrow = (const float4*)(fc1_w + o * 784 + part * 196);
        const float4* frow = (const float4*)(sfeat + part * 196);
        float sum = 0.f;
        #pragma unroll 7
        for (int k = 0; k < 49; k++) {
            float4 w4 = wrow[k];
            float4 f4 = frow[k];
            sum += w4.x * f4.x + w4.y * f4.y + w4.z * f4.z + w4.w * f4.w;
        }
        sum += __shfl_xor_sync(0xffffffffu, sum, 1);
        sum += __shfl_xor_sync(0xffffffffu, sum, 2);
        if (part == 0) sh[o] = fmaxf(sum + fc1_b[o], 0.f);
    }
    __syncthreads();

    // FC2: 10 outputs
    if (t < 10) {
        float sum = fc2_b[t];
        const float* w2 = fc2_w + t * 64;
        #pragma unroll
        for (int k = 0; k < 64; k++) sum += w2[k] * sh[k];
        out[b * 10 + t] = sum;
    }
}

extern "C" void kernel_launch(void* const* d_in, const int* in_sizes, int n_in,
                              void* d_out, int out_size) {
    const float* x      = (const float*)d_in[0];
    const float* weight = (const float*)d_in[1];
    const float* fc1_w  = (const float*)d_in[2];
    const float* fc1_b  = (const float*)d_in[3];
    const float* fc2_w  = (const float*)d_in[4];
    const float* fc2_b  = (const float*)d_in[5];
    float* out = (float*)d_out;

    const int B = in_sizes[0] / 784;  // 128
    qnet_kernel<<<B, 256>>>(x, weight, fc1_w, fc1_b, fc2_w, fc2_b, out);
}